// round 11
// baseline (speedup 1.0000x reference)
#include <cuda_runtime.h>
#include <cstdint>

// Problem constants (from reference): V=100000 vocab, D=128 dim
#define VOCAB 100000
#define DIM4  32   // 128 floats = 32 float4
#define RES_BIT (1u << 30)
#define TPW   8    // tokens per warp (grid sizing: 4096 CTAs for balance)
#define BATCH 4    // tokens per copy stage (independent LDG.128 in flight)

// Scratch: vocab -> candidate residual row. Validated in gather via
// ridx[row] == v, so no -1 fill pass is needed.
__device__ int g_remap[VOCAB];

__global__ void scatter_remap_kernel(const int* __restrict__ ridx, int R) {
    int i = blockIdx.x * blockDim.x + threadIdx.x;
    if (i < R) {
        g_remap[ridx[i]] = i;
    }
}

// Each warp owns TPW=8 tokens.
// Phase 1: lanes resolve tokens (lane & 7) in parallel (3 coalesced LDGs).
// Phase 2: copy loop, BATCH tokens per stage (BATCH independent LDG.128 in
//          flight), each lane moves one float4 per token. Streaming stores
//          keep the embedding tables L2-resident (reads are 100% L2-hit).
// __launch_bounds__(256, 8) pins regs <= 32 so 8 CTAs reside per SM.
__global__ __launch_bounds__(256, 8)
void gather_kernel(const int* __restrict__ x,
                   const int* __restrict__ ridx,     // [R] sorted, L2-hot
                   const float4* __restrict__ pre,   // [V, 32] float4
                   const float4* __restrict__ res,   // [R, 32] float4
                   float4* __restrict__ out,         // [n_tok, 32] float4
                   int n_tok, int R) {
    int warp = (blockIdx.x * blockDim.x + threadIdx.x) >> 5;
    int lane = threadIdx.x & 31;
    long long base = (long long)warp * TPW;
    if (base >= n_tok) return;
    bool full = (base + TPW <= n_tok);

    // ---- Phase 1: lanes resolve tokens base..base+TPW-1 in parallel ----
    long long mytok = base + (lane & (TPW - 1));
    int v = (mytok < n_tok) ? __ldg(x + mytok) : 0;
    int r = g_remap[v];
    bool use_res = (r >= 0) && (r < R) && (__ldg(ridx + r) == v);
    // pack: bit30 = residual flag, low bits = row index (fits: V < 2^17)
    unsigned packed = use_res ? ((unsigned)r | RES_BIT) : (unsigned)v;

    if (full) {
        // Fast path: no bounds checks, BATCH-deep load pipelining.
        #pragma unroll
        for (int t0 = 0; t0 < TPW; t0 += BATCH) {
            float4 val[BATCH];
            #pragma unroll
            for (int k = 0; k < BATCH; k++) {
                unsigned p = __shfl_sync(0xFFFFFFFFu, packed, t0 + k);
                const float4* srow = (p & RES_BIT)
                                   ? (res + (long long)(p & ~RES_BIT) * DIM4)
                                   : (pre + (long long)p * DIM4);
                val[k] = __ldg(srow + lane);
            }
            #pragma unroll
            for (int k = 0; k < BATCH; k++)
                __stcs(out + (base + t0 + k) * DIM4 + lane, val[k]);
        }
    } else {
        // Tail warp (not hit for n_tok % TPW == 0, kept for generality).
        for (int t = 0; t < TPW; t++) {
            long long tok = base + t;
            if (tok >= n_tok) break;
            unsigned p = __shfl_sync(0xFFFFFFFFu, packed, t);
            const float4* srow = (p & RES_BIT)
                               ? (res + (long long)(p & ~RES_BIT) * DIM4)
                               : (pre + (long long)p * DIM4);
            __stcs(out + tok * DIM4 + lane, __ldg(srow + lane));
        }
    }
}

extern "C" void kernel_launch(void* const* d_in, const int* in_sizes, int n_in,
                              void* d_out, int out_size) {
    // Input order per reference setup_inputs():
    //   0: x                    [B*S]   int32
    //   1: residual_index       [R]     int32
    //   2: pretrained_embedding [V*D]   float32
    //   3: residual_embedding   [R*D]   float32
    const int*    x    = (const int*)d_in[0];
    const int*    ridx = (const int*)d_in[1];
    const float4* pre  = (const float4*)d_in[2];
    const float4* res  = (const float4*)d_in[3];
    float4*       out  = (float4*)d_out;

    const int n_tok = in_sizes[0];          // B*S = 262144
    const int R     = in_sizes[1];          // 20000

    scatter_remap_kernel<<<(R + 127) / 128, 128>>>(ridx, R);

    const long long n_warps = ((long long)n_tok + TPW - 1) / TPW;
    const long long total_threads = n_warps * 32;
    const int block = 256;
    const int grid  = (int)((total_threads + block - 1) / block);
    gather_kernel<<<grid, block>>>(x, ridx, pre, res, out, n_tok, R);
}

// round 12
// speedup vs baseline: 1.0128x; 1.0128x over previous
#include <cuda_runtime.h>
#include <cstdint>

// Problem constants (from reference): V=100000 vocab, D=128 dim
#define VOCAB 100000
#define DIM4  32   // 128 floats = 32 float4
#define RES_BIT (1u << 30)
#define TPW   8    // tokens per warp (grid sizing: 4096 CTAs for balance)
#define BATCH 4    // tokens per copy stage (independent LDG.128 in flight)

// Scratch: vocab -> candidate residual row. Validated in gather via
// ridx[row] == v, so no -1 fill pass is needed.
__device__ int g_remap[VOCAB];

__global__ void scatter_remap_kernel(const int* __restrict__ ridx, int R) {
    int i = blockIdx.x * blockDim.x + threadIdx.x;
    if (i < R) {
        g_remap[ridx[i]] = i;
    }
    // PDL: allow dependent (gather) grid to begin its prologue; its
    // cudaGridDependencySynchronize() still waits for our writes to flush.
    cudaTriggerProgrammaticLaunchCompletion();
}

// Each warp owns TPW=8 tokens.
// Phase 1: lanes resolve tokens (lane & 7) in parallel (3 coalesced LDGs).
//          The x-load is issued BEFORE cudaGridDependencySynchronize() since
//          it does not depend on the scatter kernel; only the g_remap read does.
// Phase 2: copy loop, BATCH tokens per stage (BATCH independent LDG.128 in
//          flight), each lane moves one float4 per token. Streaming stores
//          keep the embedding tables L2-resident (reads are 100% L2-hit).
// __launch_bounds__(256, 8) pins regs <= 32 so 8 CTAs reside per SM.
__global__ __launch_bounds__(256, 8)
void gather_kernel(const int* __restrict__ x,
                   const int* __restrict__ ridx,     // [R] sorted, L2-hot
                   const float4* __restrict__ pre,   // [V, 32] float4
                   const float4* __restrict__ res,   // [R, 32] float4
                   float4* __restrict__ out,         // [n_tok, 32] float4
                   int n_tok, int R) {
    int warp = (blockIdx.x * blockDim.x + threadIdx.x) >> 5;
    int lane = threadIdx.x & 31;
    long long base = (long long)warp * TPW;
    if (base >= n_tok) {
        cudaGridDependencySynchronize();
        return;
    }
    bool full = (base + TPW <= n_tok);

    // ---- Phase 1a: scatter-independent token id load (overlaps scatter) ----
    long long mytok = base + (lane & (TPW - 1));
    int v = (mytok < n_tok) ? __ldg(x + mytok) : 0;

    // ---- Wait for scatter kernel's g_remap writes to be visible ----
    cudaGridDependencySynchronize();

    // ---- Phase 1b: remap + validation ----
    int r = g_remap[v];
    bool use_res = (r >= 0) && (r < R) && (__ldg(ridx + r) == v);
    // pack: bit30 = residual flag, low bits = row index (fits: V < 2^17)
    unsigned packed = use_res ? ((unsigned)r | RES_BIT) : (unsigned)v;

    if (full) {
        // Fast path: no bounds checks, BATCH-deep load pipelining.
        #pragma unroll
        for (int t0 = 0; t0 < TPW; t0 += BATCH) {
            float4 val[BATCH];
            #pragma unroll
            for (int k = 0; k < BATCH; k++) {
                unsigned p = __shfl_sync(0xFFFFFFFFu, packed, t0 + k);
                const float4* srow = (p & RES_BIT)
                                   ? (res + (long long)(p & ~RES_BIT) * DIM4)
                                   : (pre + (long long)p * DIM4);
                val[k] = __ldg(srow + lane);
            }
            #pragma unroll
            for (int k = 0; k < BATCH; k++)
                __stcs(out + (base + t0 + k) * DIM4 + lane, val[k]);
        }
    } else {
        // Tail warp (not hit for n_tok % TPW == 0, kept for generality).
        for (int t = 0; t < TPW; t++) {
            long long tok = base + t;
            if (tok >= n_tok) break;
            unsigned p = __shfl_sync(0xFFFFFFFFu, packed, t);
            const float4* srow = (p & RES_BIT)
                               ? (res + (long long)(p & ~RES_BIT) * DIM4)
                               : (pre + (long long)p * DIM4);
            __stcs(out + tok * DIM4 + lane, __ldg(srow + lane));
        }
    }
}

extern "C" void kernel_launch(void* const* d_in, const int* in_sizes, int n_in,
                              void* d_out, int out_size) {
    // Input order per reference setup_inputs():
    //   0: x                    [B*S]   int32
    //   1: residual_index       [R]     int32
    //   2: pretrained_embedding [V*D]   float32
    //   3: residual_embedding   [R*D]   float32
    const int*    x    = (const int*)d_in[0];
    const int*    ridx = (const int*)d_in[1];
    const float4* pre  = (const float4*)d_in[2];
    const float4* res  = (const float4*)d_in[3];
    float4*       out  = (float4*)d_out;

    const int n_tok = in_sizes[0];          // B*S = 262144
    const int R     = in_sizes[1];          // 20000

    scatter_remap_kernel<<<(R + 255) / 256, 256>>>(ridx, R);

    const long long n_warps = ((long long)n_tok + TPW - 1) / TPW;
    const long long total_threads = n_warps * 32;
    const int block = 256;
    const int grid  = (int)((total_threads + block - 1) / block);

    // Launch gather with Programmatic Dependent Launch: its CTAs may start
    // (and issue their x-loads) while scatter drains; the in-kernel
    // cudaGridDependencySynchronize() orders the g_remap reads.
    cudaLaunchConfig_t cfg = {};
    cfg.gridDim  = dim3((unsigned)grid, 1, 1);
    cfg.blockDim = dim3((unsigned)block, 1, 1);
    cfg.dynamicSmemBytes = 0;
    cfg.stream = 0;   // legacy default stream (same as <<<>>> above)
    cudaLaunchAttribute attr[1];
    attr[0].id = cudaLaunchAttributeProgrammaticStreamSerialization;
    attr[0].val.programmaticStreamSerializationAllowed = 1;
    cfg.attrs = attr;
    cfg.numAttrs = 1;
    cudaLaunchKernelEx(&cfg, gather_kernel, x, ridx, pre, res, out, n_tok, R);
}